// round 1
// baseline (speedup 1.0000x reference)
#include <cuda_runtime.h>
#include <cstdint>

// Problem constants
#define BB   64
#define NN   100
#define DD   32
#define E0   96      // FE[0]
#define E1   160     // FE[1]
#define E2   192     // FE[2]
#define NODES (BB*NN)          // 6400
#define ROWS  (BB*NN*NN)       // 640000
#define TILE_M 128
#define NTILES (ROWS/TILE_M)   // 5000 exactly

// Scratch (allocation-free rule: __device__ globals)
__device__ __align__(16) float g_u[NODES*E0];
__device__ __align__(16) float g_v[NODES*E0];
__device__ __align__(16) float g_agg[NODES*E2];

__device__ __forceinline__ float lrelu(float x){ return x > 0.f ? x : 0.2f*x; }

__device__ __forceinline__ unsigned long long pack2(float a, float b){
    unsigned long long r;
    asm("mov.b64 %0, {%1, %2};" : "=l"(r) : "f"(a), "f"(b));
    return r;
}
__device__ __forceinline__ unsigned long long ffma2(unsigned long long a, unsigned long long b, unsigned long long c){
    unsigned long long d;
    asm("fma.rn.f32x2 %0, %1, %2, %3;" : "=l"(d) : "l"(a), "l"(b), "l"(c));
    return d;
}
__device__ __forceinline__ float2 unpack2(unsigned long long v){
    float2 f;
    asm("mov.b64 {%0, %1}, %2;" : "=f"(f.x), "=f"(f.y) : "l"(v));
    return f;
}

// ---------------------------------------------------------------------------
// Kernel A: per-node precompute u = x@W0a + b0, v = x@W0b ; also zero g_agg
// grid = 6400, block = 192
// ---------------------------------------------------------------------------
__global__ void node_pre(const float* __restrict__ x,
                         const float* __restrict__ w0,
                         const float* __restrict__ b0)
{
    __shared__ float sx[DD];
    const int node = blockIdx.x;
    const int t = threadIdx.x;

    // zero aggregation buffer: 6400 blocks * 192 threads == 6400*192 elements
    g_agg[node*E2 + t] = 0.f;

    if (t < DD) sx[t] = x[node*DD + t];
    __syncthreads();

    float acc = 0.f;
    if (t < E0) {
        const int c = t;
        #pragma unroll
        for (int k = 0; k < DD; k++) acc += sx[k] * w0[k*E0 + c];
        g_u[node*E0 + c] = acc + b0[c];
    } else {
        const int c = t - E0;
        #pragma unroll
        for (int k = 0; k < DD; k++) acc += sx[k] * w0[(DD+k)*E0 + c];
        g_v[node*E0 + c] = acc;
    }
}

// ---------------------------------------------------------------------------
// Kernel B: fused edge MLP (layers 1,2) + segmented sum over j
// grid = 5000, block = 256, dyn smem = 194816 B
// smem layout (floats):
//   sH1 : [160][128]  @ 0        (20480)
//   sH0 : [ 96][128]  @ 20480    (12288)
//   sW  : 15360       @ 32768
//   sRed: 3*192=576   @ 48128
// ---------------------------------------------------------------------------
#define SMEM_F (48128 + 576)

__global__ __launch_bounds__(256, 1)
void edge_kernel(const float* __restrict__ w1, const float* __restrict__ b1v,
                 const float* __restrict__ w2, const float* __restrict__ b2v)
{
    extern __shared__ float smem[];
    float* sH1  = smem;           // [c][m], stride 128
    float* sH0  = smem + 20480;   // [k][m], stride 128
    float* sW   = smem + 32768;
    float* sRed = smem + 48128;

    const int tid  = threadIdx.x;
    const int base = blockIdx.x * TILE_M;

    // ---- stage W1 (96x160 = 15360 floats) into smem ----
    {
        const float4* src = (const float4*)w1;
        float4* dst = (float4*)sW;
        #pragma unroll
        for (int i = tid; i < 15360/4; i += 256) dst[i] = src[i];
    }

    // ---- build h0[k][m] = lrelu(u_i[k] + v_j[k]) ----
    for (int idx = tid; idx < (E0/4)*TILE_M; idx += 256) {
        const int kv = idx >> 7;        // 0..23 (float4 chunk of k)
        const int m  = idx & 127;
        const int r  = base + m;
        const int nu = r / 100;         // = b*100 + i
        const int b  = r / 10000;
        const int j  = r - nu*100;
        const int nv = b*100 + j;
        const float4 uu = ((const float4*)g_u)[nu*(E0/4) + kv];
        const float4 vv = ((const float4*)g_v)[nv*(E0/4) + kv];
        const int k0 = kv*4;
        sH0[(k0+0)*128 + m] = lrelu(uu.x + vv.x);
        sH0[(k0+1)*128 + m] = lrelu(uu.y + vv.y);
        sH0[(k0+2)*128 + m] = lrelu(uu.z + vv.z);
        sH0[(k0+3)*128 + m] = lrelu(uu.w + vv.w);
    }
    __syncthreads();

    const int cg = tid & 15;     // column group (fastest -> A broadcast per quarter-warp)
    const int mg = tid >> 4;     // row group
    const int m0 = mg * 8;

    // ---- GEMM1: h1 = lrelu(h0 @ W1 + b1), output transposed into sH1[c][m] ----
    {
        const int c0 = cg * 10;  // 10 cols/thread = 5 f32x2 pairs
        unsigned long long acc[8][5];
        #pragma unroll
        for (int mi = 0; mi < 8; mi++)
            #pragma unroll
            for (int t = 0; t < 5; t++) acc[mi][t] = 0ull;

        #pragma unroll 2
        for (int k = 0; k < E0; k++) {
            const float4 a0 = *(const float4*)&sH0[k*128 + m0];
            const float4 a1 = *(const float4*)&sH0[k*128 + m0 + 4];
            const unsigned long long* bp = (const unsigned long long*)&sW[k*E1 + c0];
            unsigned long long bv[5];
            #pragma unroll
            for (int t = 0; t < 5; t++) bv[t] = bp[t];
            const float am[8] = {a0.x,a0.y,a0.z,a0.w,a1.x,a1.y,a1.z,a1.w};
            #pragma unroll
            for (int mi = 0; mi < 8; mi++) {
                const unsigned long long ap = pack2(am[mi], am[mi]);
                #pragma unroll
                for (int t = 0; t < 5; t++) acc[mi][t] = ffma2(ap, bv[t], acc[mi][t]);
            }
        }
        // bias + lrelu, store transposed
        float bb[10];
        #pragma unroll
        for (int t = 0; t < 10; t++) bb[t] = b1v[c0 + t];
        #pragma unroll
        for (int mi = 0; mi < 8; mi++) {
            #pragma unroll
            for (int t = 0; t < 5; t++) {
                const float2 f = unpack2(acc[mi][t]);
                sH1[(c0+2*t  )*128 + m0 + mi] = lrelu(f.x + bb[2*t  ]);
                sH1[(c0+2*t+1)*128 + m0 + mi] = lrelu(f.y + bb[2*t+1]);
            }
        }
    }
    __syncthreads();

    // ---- GEMM2: h2 = lrelu(h1 @ W2 + b2), W2 streamed in two 80-row halves ----
    const int c0 = cg * 12;      // 12 cols/thread = 6 f32x2 pairs
    unsigned long long acc2[8][6];
    #pragma unroll
    for (int mi = 0; mi < 8; mi++)
        #pragma unroll
        for (int t = 0; t < 6; t++) acc2[mi][t] = 0ull;

    for (int p = 0; p < 2; p++) {
        // load W2 rows [80p, 80p+80): 80*192 = 15360 floats
        {
            const float4* src = (const float4*)(w2 + p*80*E2);
            float4* dst = (float4*)sW;
            #pragma unroll
            for (int i = tid; i < 15360/4; i += 256) dst[i] = src[i];
        }
        __syncthreads();
        #pragma unroll 2
        for (int kk = 0; kk < 80; kk++) {
            const int k = p*80 + kk;
            const float4 a0 = *(const float4*)&sH1[k*128 + m0];
            const float4 a1 = *(const float4*)&sH1[k*128 + m0 + 4];
            const unsigned long long* bp = (const unsigned long long*)&sW[kk*E2 + c0];
            unsigned long long bv[6];
            #pragma unroll
            for (int t = 0; t < 6; t++) bv[t] = bp[t];
            const float am[8] = {a0.x,a0.y,a0.z,a0.w,a1.x,a1.y,a1.z,a1.w};
            #pragma unroll
            for (int mi = 0; mi < 8; mi++) {
                const unsigned long long ap = pack2(am[mi], am[mi]);
                #pragma unroll
                for (int t = 0; t < 6; t++) acc2[mi][t] = ffma2(ap, bv[t], acc2[mi][t]);
            }
        }
        __syncthreads();
    }

    // ---- segmented reduction over rows (j) into g_agg[seg][c] ----
    for (int i = tid; i < 3*E2; i += 256) sRed[i] = 0.f;
    __syncthreads();

    const int seg_min = base / 100;
    const int l0 = (base + m0)     / 100 - seg_min;
    const int l7 = (base + m0 + 7) / 100 - seg_min;

    float bb2[12];
    #pragma unroll
    for (int t = 0; t < 12; t++) bb2[t] = b2v[c0 + t];

    float p0[12], p1[12];
    #pragma unroll
    for (int t = 0; t < 12; t++) { p0[t] = 0.f; p1[t] = 0.f; }

    #pragma unroll
    for (int mi = 0; mi < 8; mi++) {
        const int l = (base + m0 + mi) / 100 - seg_min;
        const bool sec = (l != l0);
        #pragma unroll
        for (int t = 0; t < 6; t++) {
            const float2 f = unpack2(acc2[mi][t]);
            const float v0 = lrelu(f.x + bb2[2*t  ]);
            const float v1 = lrelu(f.y + bb2[2*t+1]);
            if (sec) { p1[2*t] += v0; p1[2*t+1] += v1; }
            else     { p0[2*t] += v0; p0[2*t+1] += v1; }
        }
    }
    #pragma unroll
    for (int t = 0; t < 12; t++) atomicAdd(&sRed[l0*E2 + c0 + t], p0[t]);
    if (l7 != l0) {
        #pragma unroll
        for (int t = 0; t < 12; t++) atomicAdd(&sRed[l7*E2 + c0 + t], p1[t]);
    }
    __syncthreads();

    const int nseg = (base + TILE_M - 1) / 100 - seg_min + 1;   // 2 or 3
    for (int i = tid; i < nseg*E2; i += 256)
        atomicAdd(&g_agg[seg_min*E2 + i], sRed[i]);
}

// ---------------------------------------------------------------------------
// Kernel C: node MLP  h = concat(agg, x) -> 256(lr) -> 256(lr) -> 32(linear)
// grid = 100, block = 256, dyn smem = 2*256*64 floats = 131072 B
// ---------------------------------------------------------------------------
__device__ __forceinline__ void mlp_layer256(const float* __restrict__ sIn, float* __restrict__ sOut,
                                             const float* __restrict__ W, const float* __restrict__ bias,
                                             int K, int tid)
{
    const int cg = tid & 31;
    const int mg = tid >> 5;
    const int c0 = cg * 8;       // 8 cols = 4 pairs
    const int m0 = mg * 8;

    unsigned long long acc[8][4];
    #pragma unroll
    for (int mi = 0; mi < 8; mi++)
        #pragma unroll
        for (int t = 0; t < 4; t++) acc[mi][t] = 0ull;

    #pragma unroll 2
    for (int k = 0; k < K; k++) {
        const float4 a0 = *(const float4*)&sIn[k*64 + m0];
        const float4 a1 = *(const float4*)&sIn[k*64 + m0 + 4];
        const unsigned long long* bp = (const unsigned long long*)&W[k*256 + c0];
        unsigned long long bv[4];
        #pragma unroll
        for (int t = 0; t < 4; t++) bv[t] = bp[t];
        const float am[8] = {a0.x,a0.y,a0.z,a0.w,a1.x,a1.y,a1.z,a1.w};
        #pragma unroll
        for (int mi = 0; mi < 8; mi++) {
            const unsigned long long ap = pack2(am[mi], am[mi]);
            #pragma unroll
            for (int t = 0; t < 4; t++) acc[mi][t] = ffma2(ap, bv[t], acc[mi][t]);
        }
    }
    float bb[8];
    #pragma unroll
    for (int t = 0; t < 8; t++) bb[t] = bias[c0 + t];
    #pragma unroll
    for (int mi = 0; mi < 8; mi++) {
        #pragma unroll
        for (int t = 0; t < 4; t++) {
            const float2 f = unpack2(acc[mi][t]);
            sOut[(c0+2*t  )*64 + m0 + mi] = lrelu(f.x + bb[2*t  ]);
            sOut[(c0+2*t+1)*64 + m0 + mi] = lrelu(f.y + bb[2*t+1]);
        }
    }
}

__global__ __launch_bounds__(256, 1)
void node_mlp(const float* __restrict__ x,
              const float* __restrict__ w0, const float* __restrict__ b0,
              const float* __restrict__ w1, const float* __restrict__ b1,
              const float* __restrict__ w2, const float* __restrict__ b2,
              float* __restrict__ out)
{
    extern __shared__ float smem[];
    float* sA = smem;            // [k][m], stride 64, 256 rows max
    float* sB = smem + 256*64;

    const int tid  = threadIdx.x;
    const int base = blockIdx.x * 64;
    const int KIN  = E2 + DD;    // 224

    // build input: concat(agg, x), transposed [k][m]
    for (int idx = tid; idx < KIN*64; idx += 256) {
        const int k = idx / 64;
        const int m = idx % 64;
        const int node = base + m;
        sA[k*64 + m] = (k < E2) ? g_agg[node*E2 + k] : x[node*DD + (k - E2)];
    }
    __syncthreads();

    mlp_layer256(sA, sB, w0, b0, KIN, tid);   // 224 -> 256, lr
    __syncthreads();
    mlp_layer256(sB, sA, w1, b1, 256, tid);   // 256 -> 256, lr
    __syncthreads();

    // layer 3: 256 -> 32, linear
    {
        const int c  = tid & 31;
        const int mg = tid >> 5;
        const int m0 = mg * 8;
        float acc[8];
        #pragma unroll
        for (int mi = 0; mi < 8; mi++) acc[mi] = 0.f;
        #pragma unroll 4
        for (int k = 0; k < 256; k++) {
            const float4 a0 = *(const float4*)&sA[k*64 + m0];
            const float4 a1 = *(const float4*)&sA[k*64 + m0 + 4];
            const float b = w2[k*32 + c];
            acc[0] += a0.x*b; acc[1] += a0.y*b; acc[2] += a0.z*b; acc[3] += a0.w*b;
            acc[4] += a1.x*b; acc[5] += a1.y*b; acc[6] += a1.z*b; acc[7] += a1.w*b;
        }
        const float bias = b2[c];
        #pragma unroll
        for (int mi = 0; mi < 8; mi++)
            out[(base + m0 + mi)*32 + c] = acc[mi] + bias;
    }
}

// ---------------------------------------------------------------------------
extern "C" void kernel_launch(void* const* d_in, const int* in_sizes, int n_in,
                              void* d_out, int out_size)
{
    const float* x     = (const float*)d_in[0];
    const float* fe_w0 = (const float*)d_in[1];
    const float* fe_b0 = (const float*)d_in[2];
    const float* fe_w1 = (const float*)d_in[3];
    const float* fe_b1 = (const float*)d_in[4];
    const float* fe_w2 = (const float*)d_in[5];
    const float* fe_b2 = (const float*)d_in[6];
    const float* fn_w0 = (const float*)d_in[7];
    const float* fn_b0 = (const float*)d_in[8];
    const float* fn_w1 = (const float*)d_in[9];
    const float* fn_b1 = (const float*)d_in[10];
    const float* fn_w2 = (const float*)d_in[11];
    const float* fn_b2 = (const float*)d_in[12];
    float* out = (float*)d_out;

    const int edge_smem = SMEM_F * (int)sizeof(float);      // 194816
    const int mlp_smem  = 2 * 256 * 64 * (int)sizeof(float); // 131072
    cudaFuncSetAttribute(edge_kernel, cudaFuncAttributeMaxDynamicSharedMemorySize, edge_smem);
    cudaFuncSetAttribute(node_mlp,    cudaFuncAttributeMaxDynamicSharedMemorySize, mlp_smem);

    node_pre<<<NODES, 192>>>(x, fe_w0, fe_b0);
    edge_kernel<<<NTILES, 256, edge_smem>>>(fe_w1, fe_b1, fe_w2, fe_b2);
    node_mlp<<<NODES/64, 256, mlp_smem>>>(x, fn_w0, fn_b0, fn_w1, fn_b1, fn_w2, fn_b2, out);
}

// round 3
// speedup vs baseline: 2.5342x; 2.5342x over previous
#include <cuda_runtime.h>
#include <cstdint>

// Problem constants
#define BB   64
#define NN   100
#define DD   32
#define E0   96      // FE[0]
#define E1   160     // FE[1]
#define E2   192     // FE[2]
#define NODES (BB*NN)          // 6400
#define ROWS  (BB*NN*NN)       // 640000
#define TILE_M 128
#define NTILES (ROWS/TILE_M)   // 5000

// ---------------- scratch (__device__ globals; no allocs allowed) ----------
__device__ __align__(16) float    g_u[NODES*E0];
__device__ __align__(16) float    g_v[NODES*E0];
__device__ __align__(16) float    g_agg[NODES*E2];
__device__ __align__(16) uint32_t g_w1t[E1*E0];   // 15360 tf32 words, B-fragment order
__device__ __align__(16) uint32_t g_w2t[E2*E1];   // 30720 tf32 words, B-fragment order

__device__ __forceinline__ float lrelu(float x){ return x > 0.f ? x : 0.2f*x; }

__device__ __forceinline__ uint32_t f2tf(float x){
    uint32_t r;
    asm("cvt.rn.tf32.f32 %0, %1;" : "=r"(r) : "f"(x));
    return r;
}

// ---------------- f32x2 helpers (node kernels) -----------------------------
__device__ __forceinline__ unsigned long long pack2(float a, float b){
    unsigned long long r;
    asm("mov.b64 %0, {%1, %2};" : "=l"(r) : "f"(a), "f"(b));
    return r;
}
__device__ __forceinline__ unsigned long long ffma2(unsigned long long a, unsigned long long b, unsigned long long c){
    unsigned long long d;
    asm("fma.rn.f32x2 %0, %1, %2, %3;" : "=l"(d) : "l"(a), "l"(b), "l"(c));
    return d;
}
__device__ __forceinline__ float2 unpack2(unsigned long long v){
    float2 f;
    asm("mov.b64 {%0, %1}, %2;" : "=f"(f.x), "=f"(f.y) : "l"(v));
    return f;
}

// ---------------- cp.async ----------------
#define CP_ASYNC16(smem_u32, gptr) \
    asm volatile("cp.async.cg.shared.global [%0], [%1], 16;" :: "r"((uint32_t)(smem_u32)), "l"(gptr) : "memory")
#define CP_COMMIT() asm volatile("cp.async.commit_group;" ::: "memory")
#define CP_WAIT0()  asm volatile("cp.async.wait_group 0;" ::: "memory")

__device__ __forceinline__ uint32_t smem_to_u32(const void* p){
    uint32_t a;
    asm("{ .reg .u64 t; cvta.to.shared.u64 t, %1; cvt.u32.u64 %0, t; }" : "=r"(a) : "l"(p));
    return a;
}

// ---------------- mma.sync m16n8k8 tf32 (legacy path, compute_80 PTX) ------
__device__ __forceinline__ void mma8(float c[4], const uint32_t a[4], const uint32_t b[2]){
    asm volatile("mma.sync.aligned.m16n8k8.row.col.f32.tf32.tf32.f32 "
        "{%0,%1,%2,%3}, {%4,%5,%6,%7}, {%8,%9}, {%0,%1,%2,%3};"
        : "+f"(c[0]), "+f"(c[1]), "+f"(c[2]), "+f"(c[3])
        : "r"(a[0]), "r"(a[1]), "r"(a[2]), "r"(a[3]), "r"(b[0]), "r"(b[1]));
}

// ---------------------------------------------------------------------------
// w_prep: tf32-round + pack weights into B-fragment order.
// B-frag for (ks, nt): lane = (n&7)*4 + (k&3); pair slot = (k>>2)&1.
// word index = ((ks*NT + nt)*32 + lane)*2 + slot
// ---------------------------------------------------------------------------
__global__ void w_prep(const float* __restrict__ w1, const float* __restrict__ w2)
{
    const int idx = blockIdx.x * blockDim.x + threadIdx.x;
    if (idx < E0*E1) {                      // W1: k in [0,96), n in [0,160)
        const int k = idx / E1, n = idx % E1;
        const int w = (((k>>3)*20 + (n>>3))*32 + (n&7)*4 + (k&3))*2 + ((k>>2)&1);
        g_w1t[w] = f2tf(w1[k*E1 + n]);
    } else if (idx < E0*E1 + E1*E2) {       // W2: k in [0,160), n in [0,192)
        const int i2 = idx - E0*E1;
        const int k = i2 / E2, n = i2 % E2;
        const int w = (((k>>3)*24 + (n>>3))*32 + (n&7)*4 + (k&3))*2 + ((k>>2)&1);
        g_w2t[w] = f2tf(w2[k*E2 + n]);
    }
}

// ---------------------------------------------------------------------------
// node_pre: u = x@W0a + b0, v = x@W0b ; zero g_agg.  grid=6400, block=192
// ---------------------------------------------------------------------------
__global__ void node_pre(const float* __restrict__ x,
                         const float* __restrict__ w0,
                         const float* __restrict__ b0)
{
    __shared__ float sx[DD];
    const int node = blockIdx.x;
    const int t = threadIdx.x;
    g_agg[node*E2 + t] = 0.f;
    if (t < DD) sx[t] = x[node*DD + t];
    __syncthreads();
    float acc = 0.f;
    if (t < E0) {
        const int c = t;
        #pragma unroll
        for (int k = 0; k < DD; k++) acc += sx[k] * w0[k*E0 + c];
        g_u[node*E0 + c] = acc + b0[c];
    } else {
        const int c = t - E0;
        #pragma unroll
        for (int k = 0; k < DD; k++) acc += sx[k] * w0[(DD+k)*E0 + c];
        g_v[node*E0 + c] = acc;
    }
}

// ---------------------------------------------------------------------------
// edge_kernel: tf32 mma.sync. grid=5000, block=256 (8 warps), smem 196608 B
// smem words: sH0 [128][100] @0 (12800) | sH1 [128][164] @12800 (20992)
//             sW 15360 @33792 (two 7680-word halves for W2 quarters)
// sH2 (epilogue2): [192][129] @0 (24768 words), after GEMM2 completes
// ---------------------------------------------------------------------------
#define H0W 0
#define H0S 100
#define H1W 12800
#define H1S 164
#define WW  33792
#define EDGE_SMEM_BYTES ((WW + 15360)*4)   // 196608

__device__ __forceinline__ void gemm2_quarter(float c2[2][12][4],
                                              const uint32_t* __restrict__ sH1u,
                                              const uint32_t* __restrict__ wbuf,
                                              int wm, int wn, int g, int tg, int ks0)
{
    for (int ksl = 0; ksl < 5; ksl++) {
        const int ks = ks0 + ksl;
        uint32_t a[2][4];
        #pragma unroll
        for (int mt = 0; mt < 2; mt++) {
            const uint32_t* p = sH1u + (wm*32 + mt*16 + g)*H1S + ks*8 + tg;
            a[mt][0] = p[0];
            a[mt][1] = p[8*H1S];
            a[mt][2] = p[4];
            a[mt][3] = p[8*H1S + 4];
        }
        const int lane4 = g*4 + tg;
        #pragma unroll
        for (int nt = 0; nt < 12; nt++) {
            uint32_t b[2];
            *(uint2*)b = *(const uint2*)&wbuf[((ksl*24 + wn*12 + nt)*32 + lane4)*2];
            mma8(c2[0][nt], a[0], b);
            mma8(c2[1][nt], a[1], b);
        }
    }
}

__global__ __launch_bounds__(256, 1)
void edge_kernel(const float* __restrict__ b1v, const float* __restrict__ b2v)
{
    extern __shared__ float smem[];
    uint32_t* sH0u = (uint32_t*)smem + H0W;
    uint32_t* sH1u = (uint32_t*)smem + H1W;
    uint32_t* sW   = (uint32_t*)smem + WW;
    float*    sH2  = smem;                  // reused after GEMM2

    const int tid  = threadIdx.x;
    const int warp = tid >> 5;
    const int lane = tid & 31;
    const int g    = lane >> 2;
    const int tg   = lane & 3;
    const int wm   = warp >> 1;             // 0..3 (m)
    const int wn   = warp & 1;              // 0..1 (n)
    const int base = blockIdx.x * TILE_M;

    // ---- issue W1 cp.async (15360 words = 3840 x 16B) ----
    {
        const uint32_t wsm = smem_to_u32(sW);
        for (int i = tid; i < 3840; i += 256)
            CP_ASYNC16(wsm + i*16, (const void*)(g_w1t + i*4));
        CP_COMMIT();
    }

    // ---- build H0 = tf32(lrelu(u_i + v_j)) into sH0 [m][100] ----
    {
        const int r  = tid >> 1;            // 0..127
        const int kh = tid & 1;             // half of k (48 each)
        const int R  = base + r;
        const int nu = R / 100;
        const int nv = (R / 10000) * 100 + (R - nu*100);
        const float4* up = (const float4*)(g_u + nu*E0) + kh*12;
        const float4* vp = (const float4*)(g_v + nv*E0) + kh*12;
        uint32_t* dst = sH0u + r*H0S + kh*48;
        #pragma unroll
        for (int i = 0; i < 12; i++) {
            const float4 uu = up[i];
            const float4 vv = vp[i];
            uint2 w0, w1;
            w0.x = f2tf(lrelu(uu.x + vv.x));
            w0.y = f2tf(lrelu(uu.y + vv.y));
            w1.x = f2tf(lrelu(uu.z + vv.z));
            w1.y = f2tf(lrelu(uu.w + vv.w));
            *(uint2*)(dst + i*4)     = w0;
            *(uint2*)(dst + i*4 + 2) = w1;
        }
    }
    CP_WAIT0();
    __syncthreads();

    // ---- GEMM1: C1[128x160] = H0[128x96] @ W1 ----
    float c1[2][10][4];
    #pragma unroll
    for (int mt = 0; mt < 2; mt++)
        #pragma unroll
        for (int nt = 0; nt < 10; nt++)
            #pragma unroll
            for (int e = 0; e < 4; e++) c1[mt][nt][e] = 0.f;

    {
        const int lane4 = g*4 + tg;
        for (int ks = 0; ks < 12; ks++) {
            uint32_t a[2][4];
            #pragma unroll
            for (int mt = 0; mt < 2; mt++) {
                const uint32_t* p = sH0u + (wm*32 + mt*16 + g)*H0S + ks*8 + tg;
                a[mt][0] = p[0];
                a[mt][1] = p[8*H0S];
                a[mt][2] = p[4];
                a[mt][3] = p[8*H0S + 4];
            }
            #pragma unroll
            for (int nt = 0; nt < 10; nt++) {
                uint32_t b[2];
                *(uint2*)b = *(const uint2*)&sW[((ks*20 + wn*10 + nt)*32 + lane4)*2];
                mma8(c1[0][nt], a[0], b);
                mma8(c1[1][nt], a[1], b);
            }
        }
    }
    __syncthreads();   // all warps done reading W1

    // ---- issue W2 quarters 0,1 (7680 words each) ----
    {
        const uint32_t wsm = smem_to_u32(sW);
        for (int i = tid; i < 3840; i += 256)
            CP_ASYNC16(wsm + i*16, (const void*)(g_w2t + i*4));
        CP_COMMIT();
    }

    // ---- epilogue1: H1 = tf32(lrelu(C1 + b1)) -> sH1 [m][164] ----
    {
        #pragma unroll
        for (int nt = 0; nt < 10; nt++) {
            const int col = wn*80 + nt*8 + 2*tg;
            const float ba = __ldg(b1v + col);
            const float bb = __ldg(b1v + col + 1);
            #pragma unroll
            for (int mt = 0; mt < 2; mt++) {
                const int r = wm*32 + mt*16 + g;
                uint2 lo, hi;
                lo.x = f2tf(lrelu(c1[mt][nt][0] + ba));
                lo.y = f2tf(lrelu(c1[mt][nt][1] + bb));
                hi.x = f2tf(lrelu(c1[mt][nt][2] + ba));
                hi.y = f2tf(lrelu(c1[mt][nt][3] + bb));
                *(uint2*)(sH1u + r*H1S + col)       = lo;
                *(uint2*)(sH1u + (r+8)*H1S + col)   = hi;
            }
        }
    }
    CP_WAIT0();
    __syncthreads();

    // ---- GEMM2: C2[128x192] = H1[128x160] @ W2, 4 pipelined quarters ----
    float c2[2][12][4];
    #pragma unroll
    for (int mt = 0; mt < 2; mt++)
        #pragma unroll
        for (int nt = 0; nt < 12; nt++)
            #pragma unroll
            for (int e = 0; e < 4; e++) c2[mt][nt][e] = 0.f;

    const uint32_t wsm = smem_to_u32(sW);

    gemm2_quarter(c2, sH1u, sW,        wm, wn, g, tg, 0);    // q0 (buf0)
    __syncthreads();
    for (int i = tid; i < 1920; i += 256)                    // q2 -> buf0
        CP_ASYNC16(wsm + i*16, (const void*)(g_w2t + 15360 + i*4));
    CP_COMMIT();
    gemm2_quarter(c2, sH1u, sW + 7680, wm, wn, g, tg, 5);    // q1 (buf1)
    CP_WAIT0();
    __syncthreads();
    for (int i = tid; i < 1920; i += 256)                    // q3 -> buf1
        CP_ASYNC16(wsm + 7680*4 + i*16, (const void*)(g_w2t + 23040 + i*4));
    CP_COMMIT();
    gemm2_quarter(c2, sH1u, sW,        wm, wn, g, tg, 10);   // q2 (buf0)
    CP_WAIT0();
    __syncthreads();
    gemm2_quarter(c2, sH1u, sW + 7680, wm, wn, g, tg, 15);   // q3 (buf1)
    __syncthreads();

    // ---- epilogue2: h2 = lrelu(C2 + b2) -> sH2 [c][129] column-major ----
    {
        #pragma unroll
        for (int nt = 0; nt < 12; nt++) {
            const int col = wn*96 + nt*8 + 2*tg;
            const float ba = __ldg(b2v + col);
            const float bb = __ldg(b2v + col + 1);
            #pragma unroll
            for (int mt = 0; mt < 2; mt++) {
                const int r = wm*32 + mt*16 + g;
                sH2[ col   *129 + r    ] = lrelu(c2[mt][nt][0] + ba);
                sH2[(col+1)*129 + r    ] = lrelu(c2[mt][nt][1] + bb);
                sH2[ col   *129 + r + 8] = lrelu(c2[mt][nt][2] + ba);
                sH2[(col+1)*129 + r + 8] = lrelu(c2[mt][nt][3] + bb);
            }
        }
    }
    __syncthreads();

    // ---- segmented column sums (tile spans 2-3 (b,i) segments) ----
    if (tid < E2) {
        const int segmin = base / 100;
        const int r1 = (segmin + 1)*100 - base;          // 1..100
        int r2 = r1 + 100; if (r2 > 128) r2 = 128;
        const float* col = sH2 + tid*129;
        float a0 = 0.f, a1 = 0.f, a2 = 0.f;
        for (int m = 0;  m < r1;  m++) a0 += col[m];
        for (int m = r1; m < r2;  m++) a1 += col[m];
        for (int m = r2; m < 128; m++) a2 += col[m];
        atomicAdd(&g_agg[ segmin     *E2 + tid], a0);
        atomicAdd(&g_agg[(segmin + 1)*E2 + tid], a1);
        if (r2 < 128) atomicAdd(&g_agg[(segmin + 2)*E2 + tid], a2);
    }
}

// ---------------------------------------------------------------------------
// node_mlp: concat(agg,x) -> 256(lr) -> 256(lr) -> 32. grid=100, block=256
// ---------------------------------------------------------------------------
__device__ __forceinline__ void mlp_layer256(const float* __restrict__ sIn, float* __restrict__ sOut,
                                             const float* __restrict__ W, const float* __restrict__ bias,
                                             int K, int tid)
{
    const int cg = tid & 31;
    const int mg = tid >> 5;
    const int c0 = cg * 8;
    const int m0 = mg * 8;

    unsigned long long acc[8][4];
    #pragma unroll
    for (int mi = 0; mi < 8; mi++)
        #pragma unroll
        for (int t = 0; t < 4; t++) acc[mi][t] = 0ull;

    #pragma unroll 2
    for (int k = 0; k < K; k++) {
        const float4 a0 = *(const float4*)&sIn[k*64 + m0];
        const float4 a1 = *(const float4*)&sIn[k*64 + m0 + 4];
        const unsigned long long* bp = (const unsigned long long*)&W[k*256 + c0];
        unsigned long long bv[4];
        #pragma unroll
        for (int t = 0; t < 4; t++) bv[t] = bp[t];
        const float am[8] = {a0.x,a0.y,a0.z,a0.w,a1.x,a1.y,a1.z,a1.w};
        #pragma unroll
        for (int mi = 0; mi < 8; mi++) {
            const unsigned long long ap = pack2(am[mi], am[mi]);
            #pragma unroll
            for (int t = 0; t < 4; t++) acc[mi][t] = ffma2(ap, bv[t], acc[mi][t]);
        }
    }
    float bb[8];
    #pragma unroll
    for (int t = 0; t < 8; t++) bb[t] = bias[c0 + t];
    #pragma unroll
    for (int mi = 0; mi < 8; mi++) {
        #pragma unroll
        for (int t = 0; t < 4; t++) {
            const float2 f = unpack2(acc[mi][t]);
            sOut[(c0+2*t  )*64 + m0 + mi] = lrelu(f.x + bb[2*t  ]);
            sOut[(c0+2*t+1)*64 + m0 + mi] = lrelu(f.y + bb[2*t+1]);
        }
    }
}

__global__ __launch_bounds__(256, 1)
void node_mlp(const float* __restrict__ x,
              const float* __restrict__ w0, const float* __restrict__ b0,
              const float* __restrict__ w1, const float* __restrict__ b1,
              const float* __restrict__ w2, const float* __restrict__ b2,
              float* __restrict__ out)
{
    extern __shared__ float smem[];
    float* sA = smem;
    float* sB = smem + 256*64;

    const int tid  = threadIdx.x;
    const int base = blockIdx.x * 64;
    const int KIN  = E2 + DD;    // 224

    for (int idx = tid; idx < KIN*64; idx += 256) {
        const int k = idx / 64;
        const int m = idx % 64;
        const int node = base + m;
        sA[k*64 + m] = (k < E2) ? g_agg[node*E2 + k] : x[node*DD + (k - E2)];
    }
    __syncthreads();

    mlp_layer256(sA, sB, w0, b0, KIN, tid);
    __syncthreads();
    mlp_layer256(sB, sA, w1, b1, 256, tid);
    __syncthreads();

    {
        const int c  = tid & 31;
        const int mg = tid >> 5;
        const int m0 = mg * 8;
        float acc[8];
        #pragma unroll
        for (int mi = 0; mi < 8; mi++) acc[mi] = 0.f;
        #pragma unroll 4
        for (int k = 0; k < 256; k++) {
            const float4 a0 = *(const float4*)&sA[k*64 + m0];
            const float4 a1 = *(const float4*)&sA[k*64 + m0 + 4];
            const float b = w2[k*32 + c];
            acc[0] += a0.x*b; acc[1] += a0.y*b; acc[2] += a0.z*b; acc[3] += a0.w*b;
            acc[4] += a1.x*b; acc[5] += a1.y*b; acc[6] += a1.z*b; acc[7] += a1.w*b;
        }
        const float bias = b2[c];
        #pragma unroll
        for (int mi = 0; mi < 8; mi++)
            out[(base + m0 + mi)*32 + c] = acc[mi] + bias;
    }
}

// ---------------------------------------------------------------------------
extern "C" void kernel_launch(void* const* d_in, const int* in_sizes, int n_in,
                              void* d_out, int out_size)
{
    const float* x     = (const float*)d_in[0];
    const float* fe_w0 = (const float*)d_in[1];
    const float* fe_b0 = (const float*)d_in[2];
    const float* fe_w1 = (const float*)d_in[3];
    const float* fe_b1 = (const float*)d_in[4];
    const float* fe_w2 = (const float*)d_in[5];
    const float* fe_b2 = (const float*)d_in[6];
    const float* fn_w0 = (const float*)d_in[7];
    const float* fn_b0 = (const float*)d_in[8];
    const float* fn_w1 = (const float*)d_in[9];
    const float* fn_b1 = (const float*)d_in[10];
    const float* fn_w2 = (const float*)d_in[11];
    const float* fn_b2 = (const float*)d_in[12];
    float* out = (float*)d_out;

    const int edge_smem = EDGE_SMEM_BYTES;                   // 196608
    const int mlp_smem  = 2 * 256 * 64 * (int)sizeof(float); // 131072
    cudaFuncSetAttribute(edge_kernel, cudaFuncAttributeMaxDynamicSharedMemorySize, edge_smem);
    cudaFuncSetAttribute(node_mlp,    cudaFuncAttributeMaxDynamicSharedMemorySize, mlp_smem);

    w_prep<<<(E0*E1 + E1*E2 + 255)/256, 256>>>(fe_w1, fe_w2);
    node_pre<<<NODES, 192>>>(x, fe_w0, fe_b0);
    edge_kernel<<<NTILES, 256, edge_smem>>>(fe_b1, fe_b2);
    node_mlp<<<NODES/64, 256, mlp_smem>>>(x, fn_w0, fn_b0, fn_w1, fn_b1, fn_w2, fn_b2, out);
}

// round 4
// speedup vs baseline: 2.8672x; 1.1314x over previous
#include <cuda_runtime.h>
#include <cstdint>

// Problem constants
#define BB   64
#define NN   100
#define DD   32
#define E0   96
#define E1   160
#define E2   192
#define NODES (BB*NN)          // 6400
#define ROWS  (BB*NN*NN)       // 640000
#define TILE_M 128
#define NTILES (ROWS/TILE_M)   // 5000

// ---------------- scratch ----------------
__device__ __align__(16) float    g_u[NODES*E0];
__device__ __align__(16) float    g_v[NODES*E0];
__device__ __align__(16) float    g_agg[NODES*E2];
__device__ __align__(16) uint32_t g_w1t[E1*E0];     // 15360
__device__ __align__(16) uint32_t g_w2t[E2*E1];     // 30720
__device__ __align__(16) uint32_t g_nw0t[224*256];  // 57344
__device__ __align__(16) uint32_t g_nw1t[256*256];  // 65536
__device__ __align__(16) uint32_t g_nw2t[256*32];   // 8192

__device__ __forceinline__ float lrelu(float x){ return x > 0.f ? x : 0.2f*x; }

__device__ __forceinline__ uint32_t f2tf(float x){
    uint32_t r;
    asm("cvt.rn.tf32.f32 %0, %1;" : "=r"(r) : "f"(x));
    return r;
}

// ---------------- cp.async ----------------
#define CP_ASYNC16(smem_u32, gptr) \
    asm volatile("cp.async.cg.shared.global [%0], [%1], 16;" :: "r"((uint32_t)(smem_u32)), "l"(gptr) : "memory")
#define CP_COMMIT() asm volatile("cp.async.commit_group;" ::: "memory")
#define CP_WAIT0()  asm volatile("cp.async.wait_group 0;" ::: "memory")
#define CP_WAIT1()  asm volatile("cp.async.wait_group 1;" ::: "memory")
#define CP_WAIT2()  asm volatile("cp.async.wait_group 2;" ::: "memory")

__device__ __forceinline__ uint32_t smem_to_u32(const void* p){
    uint32_t a;
    asm("{ .reg .u64 t; cvta.to.shared.u64 t, %1; cvt.u32.u64 %0, t; }" : "=r"(a) : "l"(p));
    return a;
}

// ---------------- mma.sync m16n8k8 tf32 ----------------
__device__ __forceinline__ void mma8(float c[4], const uint32_t a[4], const uint32_t b[2]){
    asm volatile("mma.sync.aligned.m16n8k8.row.col.f32.tf32.tf32.f32 "
        "{%0,%1,%2,%3}, {%4,%5,%6,%7}, {%8,%9}, {%0,%1,%2,%3};"
        : "+f"(c[0]), "+f"(c[1]), "+f"(c[2]), "+f"(c[3])
        : "r"(a[0]), "r"(a[1]), "r"(a[2]), "r"(a[3]), "r"(b[0]), "r"(b[1]));
}

// ---------------------------------------------------------------------------
// w_prep: tf32-round + pack all GEMM weights into B-fragment order.
// word = ((ks*NT + nt)*32 + (n&7)*4 + (k&3))*2 + ((k>>2)&1)
// ---------------------------------------------------------------------------
__global__ void w_prep(const float* __restrict__ w1, const float* __restrict__ w2,
                       const float* __restrict__ nw0, const float* __restrict__ nw1,
                       const float* __restrict__ nw2)
{
    const int idx = blockIdx.x * blockDim.x + threadIdx.x;
    if (idx < 15360) {                       // fe_w1: K=96, N=160
        const int k = idx / E1, n = idx % E1;
        g_w1t[(((k>>3)*20 + (n>>3))*32 + (n&7)*4 + (k&3))*2 + ((k>>2)&1)] = f2tf(w1[k*E1 + n]);
    } else if (idx < 15360 + 30720) {        // fe_w2: K=160, N=192
        const int i2 = idx - 15360;
        const int k = i2 / E2, n = i2 % E2;
        g_w2t[(((k>>3)*24 + (n>>3))*32 + (n&7)*4 + (k&3))*2 + ((k>>2)&1)] = f2tf(w2[k*E2 + n]);
    } else if (idx < 46080 + 57344) {        // fn_w0: K=224, N=256
        const int i2 = idx - 46080;
        const int k = i2 / 256, n = i2 % 256;
        g_nw0t[(((k>>3)*32 + (n>>3))*32 + (n&7)*4 + (k&3))*2 + ((k>>2)&1)] = f2tf(nw0[k*256 + n]);
    } else if (idx < 103424 + 65536) {       // fn_w1: K=256, N=256
        const int i2 = idx - 103424;
        const int k = i2 / 256, n = i2 % 256;
        g_nw1t[(((k>>3)*32 + (n>>3))*32 + (n&7)*4 + (k&3))*2 + ((k>>2)&1)] = f2tf(nw1[k*256 + n]);
    } else if (idx < 168960 + 8192) {        // fn_w2: K=256, N=32
        const int i2 = idx - 168960;
        const int k = i2 / 32, n = i2 % 32;
        g_nw2t[(((k>>3)*4 + (n>>3))*32 + (n&7)*4 + (k&3))*2 + ((k>>2)&1)] = f2tf(nw2[k*32 + n]);
    }
}

// ---------------------------------------------------------------------------
// node_pre: u = x@W0a + b0, v = x@W0b ; zero g_agg.  grid=6400, block=192
// ---------------------------------------------------------------------------
__global__ void node_pre(const float* __restrict__ x,
                         const float* __restrict__ w0,
                         const float* __restrict__ b0)
{
    __shared__ float sx[DD];
    const int node = blockIdx.x;
    const int t = threadIdx.x;
    g_agg[node*E2 + t] = 0.f;
    if (t < DD) sx[t] = x[node*DD + t];
    __syncthreads();
    float acc = 0.f;
    if (t < E0) {
        const int c = t;
        #pragma unroll
        for (int k = 0; k < DD; k++) acc += sx[k] * w0[k*E0 + c];
        g_u[node*E0 + c] = acc + b0[c];
    } else {
        const int c = t - E0;
        #pragma unroll
        for (int k = 0; k < DD; k++) acc += sx[k] * w0[(DD+k)*E0 + c];
        g_v[node*E0 + c] = acc;
    }
}

// ---------------------------------------------------------------------------
// edge_kernel: tf32 mma.sync, fully-pipelined W2 prefetch.
// grid=5000, block=256, smem 206848 B
// smem words: H0 [128][100] @0 ; H1 [128][164] @0 (aliases H0, post-GEMM1)
//             SW1 @20992 (15360) | BUFA @36352 (7680) | BUFB @44032 (7680)
// sH2 epilogue reuse @0: [192][129] = 24768 words
// ---------------------------------------------------------------------------
#define H0S 100
#define H1S 164
#define SW1W  20992
#define BUFAW 36352
#define BUFBW 44032
#define EDGE_WORDS 51712
#define EDGE_SMEM_BYTES (EDGE_WORDS*4)

__device__ __forceinline__ void gemm2_quarter(float c2[2][12][4],
                                              const uint32_t* __restrict__ sH1u,
                                              const uint32_t* __restrict__ wbuf,
                                              int wm, int wn, int g, int tg, int ks0)
{
    const int lane4 = g*4 + tg;
    for (int ksl = 0; ksl < 5; ksl++) {
        const int ks = ks0 + ksl;
        uint32_t a[2][4];
        #pragma unroll
        for (int mt = 0; mt < 2; mt++) {
            const uint32_t* p = sH1u + (wm*32 + mt*16 + g)*H1S + ks*8 + tg;
            a[mt][0] = p[0];
            a[mt][1] = p[8*H1S];
            a[mt][2] = p[4];
            a[mt][3] = p[8*H1S + 4];
        }
        #pragma unroll
        for (int nt = 0; nt < 12; nt++) {
            uint32_t b[2];
            *(uint2*)b = *(const uint2*)&wbuf[((ksl*24 + wn*12 + nt)*32 + lane4)*2];
            mma8(c2[0][nt], a[0], b);
            mma8(c2[1][nt], a[1], b);
        }
    }
}

__global__ __launch_bounds__(256, 1)
void edge_kernel(const float* __restrict__ b1v, const float* __restrict__ b2v)
{
    extern __shared__ float smem[];
    uint32_t* sH0u = (uint32_t*)smem;        // stride 100
    uint32_t* sH1u = (uint32_t*)smem;        // stride 164 (aliases H0)
    uint32_t* sW1  = (uint32_t*)smem + SW1W;
    uint32_t* bufA = (uint32_t*)smem + BUFAW;
    uint32_t* bufB = (uint32_t*)smem + BUFBW;
    float*    sH2  = smem;                   // epilogue2 reuse

    const int tid  = threadIdx.x;
    const int warp = tid >> 5;
    const int lane = tid & 31;
    const int g    = lane >> 2;
    const int tg   = lane & 3;
    const int wm   = warp >> 1;
    const int wn   = warp & 1;
    const int base = blockIdx.x * TILE_M;

    const uint32_t sw1s = smem_to_u32(sW1);
    const uint32_t bufAs = smem_to_u32(bufA);
    const uint32_t bufBs = smem_to_u32(bufB);

    // G1: W1 (3840x16B)
    for (int i = tid; i < 3840; i += 256)
        CP_ASYNC16(sw1s + i*16, (const void*)(g_w1t + i*4));
    CP_COMMIT();
    // G2: W2 q0 -> bufA (1920x16B)
    for (int i = tid; i < 1920; i += 256)
        CP_ASYNC16(bufAs + i*16, (const void*)(g_w2t + i*4));
    CP_COMMIT();
    // G3: W2 q1 -> bufB
    for (int i = tid; i < 1920; i += 256)
        CP_ASYNC16(bufBs + i*16, (const void*)(g_w2t + 7680 + i*4));
    CP_COMMIT();

    // ---- build H0 = tf32(lrelu(u_i + v_j)) -> [m][100] ----
    {
        const int r  = tid >> 1;
        const int kh = tid & 1;
        const int R  = base + r;
        const int nu = R / 100;
        const int nv = (R / 10000) * 100 + (R - nu*100);
        const float4* up = (const float4*)(g_u + nu*E0) + kh*12;
        const float4* vp = (const float4*)(g_v + nv*E0) + kh*12;
        uint32_t* dst = sH0u + r*H0S + kh*48;
        #pragma unroll
        for (int i = 0; i < 12; i++) {
            const float4 uu = up[i];
            const float4 vv = vp[i];
            uint2 w0p, w1p;
            w0p.x = f2tf(lrelu(uu.x + vv.x));
            w0p.y = f2tf(lrelu(uu.y + vv.y));
            w1p.x = f2tf(lrelu(uu.z + vv.z));
            w1p.y = f2tf(lrelu(uu.w + vv.w));
            *(uint2*)(dst + i*4)     = w0p;
            *(uint2*)(dst + i*4 + 2) = w1p;
        }
    }
    CP_WAIT2();          // W1 landed
    __syncthreads();

    // ---- GEMM1: C1[128x160] = H0 @ W1 ----
    float c1[2][10][4];
    #pragma unroll
    for (int mt = 0; mt < 2; mt++)
        #pragma unroll
        for (int nt = 0; nt < 10; nt++)
            #pragma unroll
            for (int e = 0; e < 4; e++) c1[mt][nt][e] = 0.f;
    {
        const int lane4 = g*4 + tg;
        for (int ks = 0; ks < 12; ks++) {
            uint32_t a[2][4];
            #pragma unroll
            for (int mt = 0; mt < 2; mt++) {
                const uint32_t* p = sH0u + (wm*32 + mt*16 + g)*H0S + ks*8 + tg;
                a[mt][0] = p[0];
                a[mt][1] = p[8*H0S];
                a[mt][2] = p[4];
                a[mt][3] = p[8*H0S + 4];
            }
            #pragma unroll
            for (int nt = 0; nt < 10; nt++) {
                uint32_t b[2];
                *(uint2*)b = *(const uint2*)&sW1[((ks*20 + wn*10 + nt)*32 + lane4)*2];
                mma8(c1[0][nt], a[0], b);
                mma8(c1[1][nt], a[1], b);
            }
        }
    }
    __syncthreads();     // H0 + W1 dead

    // G4: W2 q2 -> SW1 region (W1 dead)
    for (int i = tid; i < 1920; i += 256)
        CP_ASYNC16(sw1s + i*16, (const void*)(g_w2t + 15360 + i*4));
    CP_COMMIT();

    // ---- epilogue1: H1 = tf32(lrelu(C1 + b1)) -> [m][164] @0 ----
    {
        #pragma unroll
        for (int nt = 0; nt < 10; nt++) {
            const int col = wn*80 + nt*8 + 2*tg;
            const float ba = __ldg(b1v + col);
            const float bb = __ldg(b1v + col + 1);
            #pragma unroll
            for (int mt = 0; mt < 2; mt++) {
                const int r = wm*32 + mt*16 + g;
                uint2 lo, hi;
                lo.x = f2tf(lrelu(c1[mt][nt][0] + ba));
                lo.y = f2tf(lrelu(c1[mt][nt][1] + bb));
                hi.x = f2tf(lrelu(c1[mt][nt][2] + ba));
                hi.y = f2tf(lrelu(c1[mt][nt][3] + bb));
                *(uint2*)(sH1u + r*H1S + col)     = lo;
                *(uint2*)(sH1u + (r+8)*H1S + col) = hi;
            }
        }
    }
    CP_WAIT2();          // q0 landed (pending <= {q1,q2})
    __syncthreads();

    // ---- GEMM2: 4 quarters, all prefetch hidden ----
    float c2[2][12][4];
    #pragma unroll
    for (int mt = 0; mt < 2; mt++)
        #pragma unroll
        for (int nt = 0; nt < 12; nt++)
            #pragma unroll
            for (int e = 0; e < 4; e++) c2[mt][nt][e] = 0.f;

    gemm2_quarter(c2, sH1u, bufA, wm, wn, g, tg, 0);     // q0
    __syncthreads();     // bufA reusable
    // G5: W2 q3 -> bufA
    for (int i = tid; i < 1920; i += 256)
        CP_ASYNC16(bufAs + i*16, (const void*)(g_w2t + 23040 + i*4));
    CP_COMMIT();
    CP_WAIT2();          // q1 landed
    __syncthreads();
    gemm2_quarter(c2, sH1u, bufB, wm, wn, g, tg, 5);     // q1
    CP_WAIT1();          // q2 landed
    __syncthreads();
    gemm2_quarter(c2, sH1u, sW1, wm, wn, g, tg, 10);     // q2
    CP_WAIT0();          // q3 landed
    __syncthreads();
    gemm2_quarter(c2, sH1u, bufA, wm, wn, g, tg, 15);    // q3
    __syncthreads();     // H1 dead

    // ---- epilogue2: h2 = lrelu(C2 + b2) -> sH2 [c][129] ----
    {
        #pragma unroll
        for (int nt = 0; nt < 12; nt++) {
            const int col = wn*96 + nt*8 + 2*tg;
            const float ba = __ldg(b2v + col);
            const float bb = __ldg(b2v + col + 1);
            #pragma unroll
            for (int mt = 0; mt < 2; mt++) {
                const int r = wm*32 + mt*16 + g;
                sH2[ col   *129 + r    ] = lrelu(c2[mt][nt][0] + ba);
                sH2[(col+1)*129 + r    ] = lrelu(c2[mt][nt][1] + bb);
                sH2[ col   *129 + r + 8] = lrelu(c2[mt][nt][2] + ba);
                sH2[(col+1)*129 + r + 8] = lrelu(c2[mt][nt][3] + bb);
            }
        }
    }
    __syncthreads();

    // ---- segmented column sums ----
    if (tid < E2) {
        const int segmin = base / 100;
        const int r1 = (segmin + 1)*100 - base;
        int r2 = r1 + 100; if (r2 > 128) r2 = 128;
        const float* col = sH2 + tid*129;
        float a0 = 0.f, a1 = 0.f, a2 = 0.f;
        for (int m = 0;  m < r1;  m++) a0 += col[m];
        for (int m = r1; m < r2;  m++) a1 += col[m];
        for (int m = r2; m < 128; m++) a2 += col[m];
        atomicAdd(&g_agg[ segmin     *E2 + tid], a0);
        atomicAdd(&g_agg[(segmin + 1)*E2 + tid], a1);
        if (r2 < 128) atomicAdd(&g_agg[(segmin + 2)*E2 + tid], a2);
    }
}

// ---------------------------------------------------------------------------
// node_mlp: tf32 mma.sync, grid=200 x 32 rows, block=256 (2m x 4n warps)
// smem: sA [32][260], sB [32][260] fp32  (66560 B)
// ---------------------------------------------------------------------------
#define NSTR 260
#define NODE_SMEM_BYTES (2*32*NSTR*4)

__device__ __forceinline__ void node_layer(const float* __restrict__ sIn, float* __restrict__ sOut,
                                           const uint32_t* __restrict__ wpk,
                                           const float* __restrict__ bias,
                                           int nks, int m0, int wn, int g, int tg, int lane)
{
    float c[8][4];
    #pragma unroll
    for (int nt = 0; nt < 8; nt++)
        #pragma unroll
        for (int e = 0; e < 4; e++) c[nt][e] = 0.f;

    for (int ks = 0; ks < nks; ks++) {
        const float* p = sIn + (m0 + g)*NSTR + ks*8 + tg;
        uint32_t a[4];
        a[0] = f2tf(p[0]);
        a[1] = f2tf(p[8*NSTR]);
        a[2] = f2tf(p[4]);
        a[3] = f2tf(p[8*NSTR + 4]);
        #pragma unroll
        for (int nt = 0; nt < 8; nt++) {
            uint32_t b[2];
            *(uint2*)b = *(const uint2*)&wpk[((ks*32 + wn*8 + nt)*32 + lane)*2];
            mma8(c[nt], a, b);
        }
    }
    #pragma unroll
    for (int nt = 0; nt < 8; nt++) {
        const int col = wn*64 + nt*8 + 2*tg;
        const float ba = __ldg(bias + col);
        const float bb = __ldg(bias + col + 1);
        sOut[(m0+g  )*NSTR + col    ] = lrelu(c[nt][0] + ba);
        sOut[(m0+g  )*NSTR + col + 1] = lrelu(c[nt][1] + bb);
        sOut[(m0+g+8)*NSTR + col    ] = lrelu(c[nt][2] + ba);
        sOut[(m0+g+8)*NSTR + col + 1] = lrelu(c[nt][3] + bb);
    }
}

__global__ __launch_bounds__(256)
void node_mlp(const float* __restrict__ x,
              const float* __restrict__ b0,
              const float* __restrict__ b1,
              const float* __restrict__ b2,
              float* __restrict__ out)
{
    extern __shared__ float smem[];
    float* sA = smem;
    float* sB = smem + 32*NSTR;

    const int tid  = threadIdx.x;
    const int warp = tid >> 5;
    const int lane = tid & 31;
    const int g    = lane >> 2;
    const int tg   = lane & 3;
    const int wm   = warp & 1;
    const int wn   = warp >> 1;
    const int m0   = wm * 16;
    const int base = blockIdx.x * 32;

    // input: concat(agg[192], x[32]) per row -> sA [m][224]
    for (int i = tid; i < 32*224; i += 256) {
        const int m = i / 224, k = i - m*224;
        const int node = base + m;
        sA[m*NSTR + k] = (k < E2) ? g_agg[node*E2 + k] : x[node*DD + (k - E2)];
    }
    __syncthreads();

    node_layer(sA, sB, g_nw0t, b0, 28, m0, wn, g, tg, lane);   // 224 -> 256
    __syncthreads();
    node_layer(sB, sA, g_nw1t, b1, 32, m0, wn, g, tg, lane);   // 256 -> 256
    __syncthreads();

    // final layer: 256 -> 32 (linear), each warp 1 n-tile of 8
    {
        float c3[4] = {0.f, 0.f, 0.f, 0.f};
        for (int ks = 0; ks < 32; ks++) {
            const float* p = sA + (m0 + g)*NSTR + ks*8 + tg;
            uint32_t a[4];
            a[0] = f2tf(p[0]);
            a[1] = f2tf(p[8*NSTR]);
            a[2] = f2tf(p[4]);
            a[3] = f2tf(p[8*NSTR + 4]);
            uint32_t b[2];
            *(uint2*)b = *(const uint2*)&g_nw2t[((ks*4 + wn)*32 + lane)*2];
            mma8(c3, a, b);
        }
        const int col = wn*8 + 2*tg;
        const float ba = __ldg(b2 + col);
        const float bb = __ldg(b2 + col + 1);
        float2 lo = {c3[0] + ba, c3[1] + bb};
        float2 hi = {c3[2] + ba, c3[3] + bb};
        *(float2*)&out[(base + m0 + g    )*32 + col] = lo;
        *(float2*)&out[(base + m0 + g + 8)*32 + col] = hi;
    }
}

// ---------------------------------------------------------------------------
extern "C" void kernel_launch(void* const* d_in, const int* in_sizes, int n_in,
                              void* d_out, int out_size)
{
    const float* x     = (const float*)d_in[0];
    const float* fe_w0 = (const float*)d_in[1];
    const float* fe_b0 = (const float*)d_in[2];
    const float* fe_w1 = (const float*)d_in[3];
    const float* fe_b1 = (const float*)d_in[4];
    const float* fe_w2 = (const float*)d_in[5];
    const float* fe_b2 = (const float*)d_in[6];
    const float* fn_w0 = (const float*)d_in[7];
    const float* fn_b0 = (const float*)d_in[8];
    const float* fn_w1 = (const float*)d_in[9];
    const float* fn_b1 = (const float*)d_in[10];
    const float* fn_w2 = (const float*)d_in[11];
    const float* fn_b2 = (const float*)d_in[12];
    float* out = (float*)d_out;

    cudaFuncSetAttribute(edge_kernel, cudaFuncAttributeMaxDynamicSharedMemorySize, EDGE_SMEM_BYTES);
    cudaFuncSetAttribute(node_mlp,    cudaFuncAttributeMaxDynamicSharedMemorySize, NODE_SMEM_BYTES);

    w_prep<<<(177152 + 255)/256, 256>>>(fe_w1, fe_w2, fn_w0, fn_w1, fn_w2);
    node_pre<<<NODES, 192>>>(x, fe_w0, fe_b0);
    edge_kernel<<<NTILES, 256, EDGE_SMEM_BYTES>>>(fe_b1, fe_b2);
    node_mlp<<<NODES/32, 256, NODE_SMEM_BYTES>>>(x, fn_b0, fn_b1, fn_b2, out);
}

// round 5
// speedup vs baseline: 4.5234x; 1.5776x over previous
#include <cuda_runtime.h>
#include <cuda_fp16.h>
#include <cstdint>

// Problem constants
#define BB   64
#define NN   100
#define DD   32
#define E0   96
#define E1   160
#define E2   192
#define NODES (BB*NN)          // 6400
#define ROWS  (BB*NN*NN)       // 640000
#define TIL   64
#define NTILES (ROWS/TIL)      // 10000

// ---------------- scratch ----------------
__device__ __align__(16) float    g_u[NODES*E0];
__device__ __align__(16) float    g_v[NODES*E0];
__device__ __align__(16) float    g_agg[NODES*E2];
__device__ __align__(16) uint32_t g_w1h[6*20*64];    // 7680  (fe_w1 fp16 frags)
__device__ __align__(16) uint32_t g_w2h[10*24*64];   // 15360 (fe_w2)
__device__ __align__(16) uint32_t g_nw0h[14*32*64];  // 28672 (fn_w0)
__device__ __align__(16) uint32_t g_nw1h[16*32*64];  // 32768 (fn_w1)
__device__ __align__(16) uint32_t g_nw2h[16*4*64];   // 4096  (fn_w2)

__device__ __forceinline__ float lrelu(float x){ return x > 0.f ? x : 0.2f*x; }

__device__ __forceinline__ uint32_t h2pack(float a, float b){
    __half2 h = __floats2half2_rn(a, b);
    return *(uint32_t*)&h;
}

// ---------------- cp.async ----------------
#define CP_ASYNC16(smem_u32, gptr) \
    asm volatile("cp.async.cg.shared.global [%0], [%1], 16;" :: "r"((uint32_t)(smem_u32)), "l"(gptr) : "memory")
#define CP_COMMIT() asm volatile("cp.async.commit_group;" ::: "memory")
#define CP_WAIT0()  asm volatile("cp.async.wait_group 0;" ::: "memory")

__device__ __forceinline__ uint32_t smem_to_u32(const void* p){
    uint32_t a;
    asm("{ .reg .u64 t; cvta.to.shared.u64 t, %1; cvt.u32.u64 %0, t; }" : "=r"(a) : "l"(p));
    return a;
}

// ---------------- mma.sync m16n8k16 fp16 (fp32 accum) ----------------
__device__ __forceinline__ void mma16(float c[4], const uint32_t a[4], const uint32_t b[2]){
    asm volatile("mma.sync.aligned.m16n8k16.row.col.f32.f16.f16.f32 "
        "{%0,%1,%2,%3}, {%4,%5,%6,%7}, {%8,%9}, {%0,%1,%2,%3};"
        : "+f"(c[0]), "+f"(c[1]), "+f"(c[2]), "+f"(c[3])
        : "r"(a[0]), "r"(a[1]), "r"(a[2]), "r"(a[3]), "r"(b[0]), "r"(b[1]));
}

// ---------------------------------------------------------------------------
// w_prep: round weights to fp16 + pack into m16n8k16 B-fragment order.
// For (ks, nt): lane=g*4+tg, reg r: half2 = (W[k0][n], W[k0+1][n]),
//   k0 = ks*16 + 2*tg + 8*r, n = nt*8 + g.
// ---------------------------------------------------------------------------
__device__ __forceinline__ void packW(uint32_t* dst, const float* W, int N, int NT, int idx){
    const int ks  = idx / (NT*64);
    const int rem = idx - ks*(NT*64);
    const int nt  = rem >> 6;
    const int l2  = rem & 63;
    const int lane = l2 >> 1, r = l2 & 1;
    const int gg = lane >> 2, tg = lane & 3;
    const int k0 = ks*16 + 2*tg + 8*r;
    const int n  = nt*8 + gg;
    dst[idx] = h2pack(W[k0*N + n], W[(k0+1)*N + n]);
}

__global__ void w_prep(const float* __restrict__ w1, const float* __restrict__ w2,
                       const float* __restrict__ nw0, const float* __restrict__ nw1,
                       const float* __restrict__ nw2)
{
    const int idx = blockIdx.x * blockDim.x + threadIdx.x;
    if      (idx < 7680)                 packW(g_w1h,  w1,  E1,  20, idx);
    else if (idx < 7680+15360)           packW(g_w2h,  w2,  E2,  24, idx - 7680);
    else if (idx < 23040+28672)          packW(g_nw0h, nw0, 256, 32, idx - 23040);
    else if (idx < 51712+32768)          packW(g_nw1h, nw1, 256, 32, idx - 51712);
    else if (idx < 84480+4096)           packW(g_nw2h, nw2, 32,  4,  idx - 84480);
}

// ---------------------------------------------------------------------------
// node_pre: u = x@W0a + b0, v = x@W0b ; zero g_agg.  grid=6400, block=192
// ---------------------------------------------------------------------------
__global__ void node_pre(const float* __restrict__ x,
                         const float* __restrict__ w0,
                         const float* __restrict__ b0)
{
    __shared__ float sx[DD];
    const int node = blockIdx.x;
    const int t = threadIdx.x;
    g_agg[node*E2 + t] = 0.f;
    if (t < DD) sx[t] = x[node*DD + t];
    __syncthreads();
    float acc = 0.f;
    if (t < E0) {
        const int c = t;
        #pragma unroll
        for (int k = 0; k < DD; k++) acc += sx[k] * w0[k*E0 + c];
        g_u[node*E0 + c] = acc + b0[c];
    } else {
        const int c = t - E0;
        #pragma unroll
        for (int k = 0; k < DD; k++) acc += sx[k] * w0[(DD+k)*E0 + c];
        g_v[node*E0 + c] = acc;
    }
}

// ---------------------------------------------------------------------------
// edge_kernel: persistent, fp16 mma, weights smem-resident.
// grid=304, block=256 (8 warps = 2m x 4n), smem = 28416 words = 113664 B
// smem words: region [0,5376): H0 (stride 52w) / H1 (stride 84w) / sPart(768)
//             sW1 @5376 (7680) | sW2 @13056 (15360)
// ---------------------------------------------------------------------------
#define H0S 52     // words per row (96 halves + pad)
#define H1S 84     // words per row (160 halves + pad)
#define SW1W 5376
#define SW2W 13056
#define EDGE_WORDS 28416
#define EDGE_SMEM_BYTES (EDGE_WORDS*4)

__global__ __launch_bounds__(256, 2)
void edge_kernel(const float* __restrict__ b1v, const float* __restrict__ b2v)
{
    extern __shared__ uint32_t smem_u[];
    uint32_t* region = smem_u;
    uint32_t* sW1 = smem_u + SW1W;
    uint32_t* sW2 = smem_u + SW2W;
    float*    sPart = (float*)smem_u;       // [wm*2+seg][192], 768 words

    const int tid  = threadIdx.x;
    const int warp = tid >> 5;
    const int lane = tid & 31;
    const int g    = lane >> 2;
    const int tg   = lane & 3;
    const int wm   = warp >> 2;             // 0..1
    const int wn   = warp & 3;              // 0..3

    // ---- preload weights once ----
    {
        const uint32_t s1 = smem_to_u32(sW1);
        for (int i = tid; i < 1920; i += 256) CP_ASYNC16(s1 + i*16, (const void*)(g_w1h + i*4));
        const uint32_t s2 = smem_to_u32(sW2);
        for (int i = tid; i < 3840; i += 256) CP_ASYNC16(s2 + i*16, (const void*)(g_w2h + i*4));
        CP_COMMIT();
        CP_WAIT0();
    }
    __syncthreads();

    for (int tile = blockIdx.x; tile < NTILES; tile += gridDim.x) {
        const int base = tile * TIL;

        // ---- build H0 = fp16(lrelu(u_i + v_j)) -> region [row][52w] ----
        {
            const int row = tid >> 2;
            const int kq  = tid & 3;
            const int R   = base + row;
            const int nu  = R / 100;
            const int nv  = (R / 10000) * 100 + (R - nu*100);
            const float4* up = (const float4*)(g_u + nu*E0) + kq*6;
            const float4* vp = (const float4*)(g_v + nv*E0) + kq*6;
            uint32_t* dst = region + row*H0S + kq*12;
            #pragma unroll
            for (int i = 0; i < 6; i++) {
                const float4 uu = up[i];
                const float4 vv = vp[i];
                uint2 w;
                w.x = h2pack(lrelu(uu.x + vv.x), lrelu(uu.y + vv.y));
                w.y = h2pack(lrelu(uu.z + vv.z), lrelu(uu.w + vv.w));
                *(uint2*)(dst + i*2) = w;
            }
        }
        __syncthreads();

        // ---- GEMM1: C1[64x160] = H0[64x96] @ W1, K=96 -> 6 ks ----
        float c1[2][5][4];
        #pragma unroll
        for (int mt = 0; mt < 2; mt++)
            #pragma unroll
            for (int nt = 0; nt < 5; nt++)
                #pragma unroll
                for (int e = 0; e < 4; e++) c1[mt][nt][e] = 0.f;

        #pragma unroll
        for (int ks = 0; ks < 6; ks++) {
            uint32_t a[2][4];
            #pragma unroll
            for (int mt = 0; mt < 2; mt++) {
                const uint32_t* p = region + (wm*32 + mt*16 + g)*H0S + ks*8 + tg;
                a[mt][0] = p[0];
                a[mt][1] = p[8*H0S];
                a[mt][2] = p[4];
                a[mt][3] = p[8*H0S + 4];
            }
            #pragma unroll
            for (int nt = 0; nt < 5; nt++) {
                uint32_t b[2];
                *(uint2*)b = *(const uint2*)&sW1[((ks*20 + wn*5 + nt)*32 + lane)*2];
                mma16(c1[0][nt], a[0], b);
                mma16(c1[1][nt], a[1], b);
            }
        }
        __syncthreads();   // H0 dead; region becomes H1

        // ---- epilogue1: H1 = fp16(lrelu(C1 + b1)) -> region [row][84w] ----
        #pragma unroll
        for (int nt = 0; nt < 5; nt++) {
            const int col = wn*40 + nt*8 + 2*tg;
            const float ba = __ldg(b1v + col);
            const float bb = __ldg(b1v + col + 1);
            #pragma unroll
            for (int mt = 0; mt < 2; mt++) {
                const int r0 = wm*32 + mt*16 + g;
                region[r0*H1S + (col>>1)]     = h2pack(lrelu(c1[mt][nt][0] + ba), lrelu(c1[mt][nt][1] + bb));
                region[(r0+8)*H1S + (col>>1)] = h2pack(lrelu(c1[mt][nt][2] + ba), lrelu(c1[mt][nt][3] + bb));
            }
        }
        __syncthreads();

        // ---- GEMM2: C2[64x192] = H1[64x160] @ W2, K=160 -> 10 ks ----
        float c2[2][6][4];
        #pragma unroll
        for (int mt = 0; mt < 2; mt++)
            #pragma unroll
            for (int nt = 0; nt < 6; nt++)
                #pragma unroll
                for (int e = 0; e < 4; e++) c2[mt][nt][e] = 0.f;

        #pragma unroll
        for (int ks = 0; ks < 10; ks++) {
            uint32_t a[2][4];
            #pragma unroll
            for (int mt = 0; mt < 2; mt++) {
                const uint32_t* p = region + (wm*32 + mt*16 + g)*H1S + ks*8 + tg;
                a[mt][0] = p[0];
                a[mt][1] = p[8*H1S];
                a[mt][2] = p[4];
                a[mt][3] = p[8*H1S + 4];
            }
            #pragma unroll
            for (int nt = 0; nt < 6; nt++) {
                uint32_t b[2];
                *(uint2*)b = *(const uint2*)&sW2[((ks*24 + wn*6 + nt)*32 + lane)*2];
                mma16(c2[0][nt], a[0], b);
                mma16(c2[1][nt], a[1], b);
            }
        }

        // ---- in-register segmented reduce over rows (<=2 segments/tile) ----
        const int s0 = base / 100;
        int r1 = (s0 + 1)*100 - base;  if (r1 > TIL) r1 = TIL;

        float acc[2][12];
        #pragma unroll
        for (int s = 0; s < 2; s++)
            #pragma unroll
            for (int i = 0; i < 12; i++) acc[s][i] = 0.f;

        #pragma unroll
        for (int nt = 0; nt < 6; nt++) {
            const int col = wn*48 + nt*8 + 2*tg;
            const float ba = __ldg(b2v + col);
            const float bb = __ldg(b2v + col + 1);
            #pragma unroll
            for (int mt = 0; mt < 2; mt++) {
                const int offA = wm*32 + mt*16 + g;      // rows for e=0,1
                const int offB = offA + 8;               // rows for e=2,3
                const int sA = (offA >= r1);
                const int sB = (offB >= r1);
                acc[sA][nt*2  ] += lrelu(c2[mt][nt][0] + ba);
                acc[sA][nt*2+1] += lrelu(c2[mt][nt][1] + bb);
                acc[sB][nt*2  ] += lrelu(c2[mt][nt][2] + ba);
                acc[sB][nt*2+1] += lrelu(c2[mt][nt][3] + bb);
            }
        }
        // reduce across g (lanes differing in bits 2..4)
        #pragma unroll
        for (int off = 4; off < 32; off <<= 1)
            #pragma unroll
            for (int s = 0; s < 2; s++)
                #pragma unroll
                for (int i = 0; i < 12; i++)
                    acc[s][i] += __shfl_xor_sync(0xFFFFFFFFu, acc[s][i], off);

        __syncthreads();   // all warps done reading H1; sPart region free

        if (g == 0) {
            #pragma unroll
            for (int nt = 0; nt < 6; nt++) {
                const int col = wn*48 + nt*8 + 2*tg;
                sPart[(wm*2 + 0)*192 + col    ] = acc[0][nt*2];
                sPart[(wm*2 + 0)*192 + col + 1] = acc[0][nt*2+1];
                sPart[(wm*2 + 1)*192 + col    ] = acc[1][nt*2];
                sPart[(wm*2 + 1)*192 + col + 1] = acc[1][nt*2+1];
            }
        }
        __syncthreads();

        if (tid < 192) {
            const float v0 = sPart[tid] + sPart[384 + tid];
            atomicAdd(&g_agg[s0*E2 + tid], v0);
            if (r1 < TIL) {
                const float v1 = sPart[192 + tid] + sPart[576 + tid];
                atomicAdd(&g_agg[(s0+1)*E2 + tid], v1);
            }
        }
        __syncthreads();   // sPart consumed before next tile's H0 build
    }
}

// ---------------------------------------------------------------------------
// node_mlp: fp16 mma, 16 rows/CTA, grid=400, block=256 (8 n-warps)
// smem: bufA [16][132w] + bufB [16][132w] = 4224 words
// ---------------------------------------------------------------------------
#define NBS 132
#define NODE_SMEM_BYTES (2*16*NBS*4)

__global__ __launch_bounds__(256)
void node_mlp(const float* __restrict__ x,
              const float* __restrict__ b0,
              const float* __restrict__ b1,
              const float* __restrict__ b2,
              float* __restrict__ out)
{
    extern __shared__ uint32_t smem_u[];
    uint32_t* bufA = smem_u;
    uint32_t* bufB = smem_u + 16*NBS;

    const int tid  = threadIdx.x;
    const int warp = tid >> 5;
    const int lane = tid & 31;
    const int g    = lane >> 2;
    const int tg   = lane & 3;
    const int base = blockIdx.x * 16;

    // build input: concat(agg[192], x[32]) -> fp16 bufA [row][132w]
    for (int i = tid; i < 16*112; i += 256) {
        const int row = i / 112;
        const int kw  = i - row*112;
        const int k   = kw*2;
        const int node = base + row;
        float v0, v1;
        if (k < E2) { v0 = g_agg[node*E2 + k]; v1 = g_agg[node*E2 + k + 1]; }
        else        { v0 = x[node*DD + (k - E2)]; v1 = x[node*DD + (k - E2) + 1]; }
        bufA[row*NBS + kw] = h2pack(v0, v1);
    }
    __syncthreads();

    // layer0: 224 -> 256 (14 ks), layer1: 256 -> 256 (16 ks)
    for (int layer = 0; layer < 2; layer++) {
        const uint32_t* sIn = layer ? bufB : bufA;
        uint32_t* sOut      = layer ? bufA : bufB;
        const uint32_t* wpk = layer ? g_nw1h : g_nw0h;
        const float* bias   = layer ? b1 : b0;
        const int nks       = layer ? 16 : 14;

        float c[4][4];
        #pragma unroll
        for (int nt = 0; nt < 4; nt++)
            #pragma unroll
            for (int e = 0; e < 4; e++) c[nt][e] = 0.f;

        for (int ks = 0; ks < nks; ks++) {
            const uint32_t* p = sIn + g*NBS + ks*8 + tg;
            uint32_t a[4];
            a[0] = p[0];
            a[1] = p[8*NBS];
            a[2] = p[4];
            a[3] = p[8*NBS + 4];
            #pragma unroll
            for (int nt = 0; nt < 4; nt++) {
                uint32_t b[2];
                *(uint2*)b = *(const uint2*)&wpk[((ks*32 + warp*4 + nt)*32 + lane)*2];
                mma16(c[nt], a, b);
            }
        }
        __syncthreads();  // before overwriting sOut (aliases nothing, but ordering w/ next read)
        #pragma unroll
        for (int nt = 0; nt < 4; nt++) {
            const int col = warp*32 + nt*8 + 2*tg;
            const float ba = __ldg(bias + col);
            const float bb = __ldg(bias + col + 1);
            sOut[g*NBS + (col>>1)]     = h2pack(lrelu(c[nt][0] + ba), lrelu(c[nt][1] + bb));
            sOut[(g+8)*NBS + (col>>1)] = h2pack(lrelu(c[nt][2] + ba), lrelu(c[nt][3] + bb));
        }
        __syncthreads();
    }

    // layer2: 256 -> 32 linear (warps 0-3 only, 16 ks)
    if (warp < 4) {
        float c3[4] = {0.f, 0.f, 0.f, 0.f};
        for (int ks = 0; ks < 16; ks++) {
            const uint32_t* p = bufA + g*NBS + ks*8 + tg;
            uint32_t a[4];
            a[0] = p[0];
            a[1] = p[8*NBS];
            a[2] = p[4];
            a[3] = p[8*NBS + 4];
            uint32_t b[2];
            *(uint2*)b = *(const uint2*)&g_nw2h[((ks*4 + warp)*32 + lane)*2];
            mma16(c3, a, b);
        }
        const int col = warp*8 + 2*tg;
        const float ba = __ldg(b2 + col);
        const float bb = __ldg(b2 + col + 1);
        float2 lo = {c3[0] + ba, c3[1] + bb};
        float2 hi = {c3[2] + ba, c3[3] + bb};
        *(float2*)&out[(base + g    )*32 + col] = lo;
        *(float2*)&out[(base + g + 8)*32 + col] = hi;
    }
}

// ---------------------------------------------------------------------------
extern "C" void kernel_launch(void* const* d_in, const int* in_sizes, int n_in,
                              void* d_out, int out_size)
{
    const float* x     = (const float*)d_in[0];
    const float* fe_w0 = (const float*)d_in[1];
    const float* fe_b0 = (const float*)d_in[2];
    const float* fe_w1 = (const float*)d_in[3];
    const float* fe_b1 = (const float*)d_in[4];
    const float* fe_w2 = (const float*)d_in[5];
    const float* fe_b2 = (const float*)d_in[6];
    const float* fn_w0 = (const float*)d_in[7];
    const float* fn_b0 = (const float*)d_in[8];
    const float* fn_w1 = (const float*)d_in[9];
    const float* fn_b1 = (const float*)d_in[10];
    const float* fn_w2 = (const float*)d_in[11];
    const float* fn_b2 = (const float*)d_in[12];
    float* out = (float*)d_out;

    cudaFuncSetAttribute(edge_kernel, cudaFuncAttributeMaxDynamicSharedMemorySize, EDGE_SMEM_BYTES);
    cudaFuncSetAttribute(node_mlp,    cudaFuncAttributeMaxDynamicSharedMemorySize, NODE_SMEM_BYTES);

    w_prep<<<(88576 + 255)/256, 256>>>(fe_w1, fe_w2, fn_w0, fn_w1, fn_w2);
    node_pre<<<NODES, 192>>>(x, fe_w0, fe_b0);
    edge_kernel<<<304, 256, EDGE_SMEM_BYTES>>>(fe_b1, fe_b2);
    node_mlp<<<NODES/16, 256, NODE_SMEM_BYTES>>>(x, fn_b0, fn_b1, fn_b2, out);
}